// round 15
// baseline (speedup 1.0000x reference)
#include <cuda_runtime.h>
#include <cuda_bf16.h>

typedef unsigned long long u64;
#define FULLM 0xffffffffu
#define NMAXP 1000000
#define VMAXP 200000

// ---- packed f32x2 helpers ----
__device__ __forceinline__ u64 pack2(float a, float b) {
  u64 r;
  asm("mov.b64 %0, {%1, %2};" : "=l"(r) : "r"(__float_as_uint(a)), "r"(__float_as_uint(b)));
  return r;
}
__device__ __forceinline__ void unpack2(u64 v, float& a, float& b) {
  unsigned x, y;
  asm("mov.b64 {%0, %1}, %2;" : "=r"(x), "=r"(y) : "l"(v));
  a = __uint_as_float(x); b = __uint_as_float(y);
}
__device__ __forceinline__ u64 bcast2(float v) { return pack2(v, v); }
__device__ __forceinline__ u64 fma2(u64 a, u64 b, u64 c) {
  u64 r; asm("fma.rn.f32x2 %0, %1, %2, %3;" : "=l"(r) : "l"(a), "l"(b), "l"(c)); return r;
}
__device__ __forceinline__ u64 add2(u64 a, u64 b) {
  u64 r; asm("add.rn.f32x2 %0, %1, %2;" : "=l"(r) : "l"(a), "l"(b)); return r;
}
__device__ __forceinline__ u64 relu2(u64 v) {
  float a, b; unpack2(v, a, b);
  return pack2(fmaxf(a, 0.0f), fmaxf(b, 0.0f));
}
__device__ __forceinline__ u64 lds2(const float* p) {
  float2 v = *reinterpret_cast<const float2*>(p); return pack2(v.x, v.y);
}
__device__ __forceinline__ void ld2q(const float* p, u64& w0, u64& w1) {
  float4 v = *reinterpret_cast<const float4*>(p);
  w0 = pack2(v.x, v.y); w1 = pack2(v.z, v.w);
}

// ---- legacy tensor-core mma (sm_80+ path, works on bare sm_103) ----
__device__ __forceinline__ void mma16816(float* d, const unsigned* a, unsigned b0, unsigned b1) {
  asm volatile(
      "mma.sync.aligned.m16n8k16.row.col.f32.bf16.bf16.f32 "
      "{%0,%1,%2,%3}, {%4,%5,%6,%7}, {%8,%9}, {%0,%1,%2,%3};"
      : "+f"(d[0]), "+f"(d[1]), "+f"(d[2]), "+f"(d[3])
      : "r"(a[0]), "r"(a[1]), "r"(a[2]), "r"(a[3]), "r"(b0), "r"(b1));
}

struct WP {
  const float *pe_w1,*pe_g1,*pe_b1,*pe_w2,*pe_g2,*pe_b2,*pe_w3,*pe_g3,*pe_b3;
  const float *ve_w1,*ve_g1,*ve_b1,*ve_w2,*ve_g2,*ve_b2;
  const float *fu_w,*fu_g,*fu_b;
  const float *cl_w1,*cl_g1,*cl_b1;
  const float *ax_w1,*ax_g1,*ax_b1;
  const int   *pv_raw;
};

// ---- folded weights ----
static __device__ float g_w_pe1[4*32],  g_b_pe1[32];
static __device__ float g_w_pe2[32*64], g_b_pe2[64];
static __device__ float g_w_pe3[64*32], g_b_pe3[32];
static __device__ float g_w_ve1[32*32], g_b_ve1[32];
static __device__ float g_w_ve2[32*32], g_b_ve2[32];
static __device__ float g_w_fu [64*64], g_b_fu [64];
static __device__ float g_w_cl1[64*32], g_b_cl1[32];
static __device__ float g_w_ax1[32*32], g_b_ax1[32];
// fu weights bf16 hi/lo, n-major k-pair: [n][kp]
static __device__ unsigned g_fu_bh2[64*32], g_fu_bl2[64*32];
// cl_w1 bf16 hi/lo, n-major k-pair: [n][kp]  (n<32, kp<32)
static __device__ unsigned g_cl_bh2[32*32], g_cl_bl2[32*32];

// ---- scratch ----
static __device__ int      g_pv_is64;
static __device__ int      g_pv[NMAXP];
static __device__ float2   g_pf2[16*NMAXP];
static __device__ unsigned g_vmax[VMAXP*32];
static __device__ float    g_vf[VMAXP*32];
static __device__ float2   g_fused2[32*NMAXP];
static __device__ float    g_bsum[4*64];
static __device__ unsigned g_bcnt[4];
static __device__ float    g_gp1[4*64];

__device__ __forceinline__ void fold_w(float* dw, float* db,
    const float* W, const float* g, const float* b, int fi, int fo) {
  const float inv = 1.0f / sqrtf(1.0f + 1e-5f);
  for (int t = threadIdx.x; t < fi*fo; t += blockDim.x) dw[t] = W[t] * (g[t % fo] * inv);
  for (int t = threadIdx.x; t < fo;    t += blockDim.x) db[t] = b[t];
}

__global__ void k_prep(WP p) {
  fold_w(g_w_pe1, g_b_pe1, p.pe_w1, p.pe_g1, p.pe_b1, 4, 32);
  fold_w(g_w_pe2, g_b_pe2, p.pe_w2, p.pe_g2, p.pe_b2, 32, 64);
  fold_w(g_w_pe3, g_b_pe3, p.pe_w3, p.pe_g3, p.pe_b3, 64, 32);
  fold_w(g_w_ve1, g_b_ve1, p.ve_w1, p.ve_g1, p.ve_b1, 32, 32);
  fold_w(g_w_ve2, g_b_ve2, p.ve_w2, p.ve_g2, p.ve_b2, 32, 32);
  fold_w(g_w_fu,  g_b_fu,  p.fu_w,  p.fu_g,  p.fu_b,  64, 64);
  fold_w(g_w_cl1, g_b_cl1, p.cl_w1, p.cl_g1, p.cl_b1, 64, 32);
  fold_w(g_w_ax1, g_b_ax1, p.ax_w1, p.ax_g1, p.ax_b1, 32, 32);
  __syncthreads();
  for (int t = threadIdx.x; t < 64*32; t += blockDim.x) {
    int n = t >> 5, kp = t & 31;
    float w0 = g_w_fu[(2*kp)*64 + n];
    float w1 = g_w_fu[(2*kp+1)*64 + n];
    __nv_bfloat16 h0 = __float2bfloat16_rn(w0);
    __nv_bfloat16 h1 = __float2bfloat16_rn(w1);
    float l0 = w0 - __bfloat162float(h0);
    float l1 = w1 - __bfloat162float(h1);
    g_fu_bh2[t] = ((unsigned)__bfloat16_as_ushort(h1) << 16) | __bfloat16_as_ushort(h0);
    g_fu_bl2[t] = ((unsigned)__bfloat16_as_ushort(__float2bfloat16_rn(l1)) << 16)
                | __bfloat16_as_ushort(__float2bfloat16_rn(l0));
  }
  for (int t = threadIdx.x; t < 32*32; t += blockDim.x) {
    int n = t >> 5, kp = t & 31;
    float w0 = g_w_cl1[(2*kp)*32 + n];
    float w1 = g_w_cl1[(2*kp+1)*32 + n];
    __nv_bfloat16 h0 = __float2bfloat16_rn(w0);
    __nv_bfloat16 h1 = __float2bfloat16_rn(w1);
    float l0 = w0 - __bfloat162float(h0);
    float l1 = w1 - __bfloat162float(h1);
    g_cl_bh2[t] = ((unsigned)__bfloat16_as_ushort(h1) << 16) | __bfloat16_as_ushort(h0);
    g_cl_bl2[t] = ((unsigned)__bfloat16_as_ushort(__float2bfloat16_rn(l1)) << 16)
                | __bfloat16_as_ushort(__float2bfloat16_rn(l0));
  }
  if (threadIdx.x == 0) {
    int z = 1;
    for (int k = 1; k < 128; k += 2) if (p.pv_raw[k] != 0) { z = 0; break; }
    g_pv_is64 = z;
  }
}

__global__ void k_init(const void* pv_raw, int N, int V) {
  int i = blockIdx.x * blockDim.x + threadIdx.x;
  if (i < N) {
    g_pv[i] = g_pv_is64 ? (int)((const long long*)pv_raw)[i]
                        : ((const int*)pv_raw)[i];
  }
  if (i < 32*V) g_vmax[i] = 0u;
  if (i < 256)  g_bsum[i] = 0.0f;
  if (i < 4)    g_bcnt[i] = 0u;
}

// ---- per-point MLP 4->32->64->32, 2 points/thread (R8) ----
__global__ void __launch_bounds__(128, 3) k_points(const float* __restrict__ points, int N) {
  __shared__ __align__(16) float sw1[4*32], sw2[32*64], sw3[64*32];
  __shared__ __align__(16) float sb1[32], sb2[64], sb3[32];
  int t = blockIdx.x * 128 + threadIdx.x;
  int i0 = 2*t, i1 = i0 + 1;
  bool act0 = i0 < N, act1 = i1 < N;
  float x0[4], x1[4]; int pv0 = 0, pv1 = 0;
  if (act0) {
    const float* p = points + (size_t)i0 * 5;
    x0[0]=p[1]; x0[1]=p[2]; x0[2]=p[3]; x0[3]=p[4];
    pv0 = g_pv[i0];
  }
  if (act1) {
    const float* p = points + (size_t)i1 * 5;
    x1[0]=p[1]; x1[1]=p[2]; x1[2]=p[3]; x1[3]=p[4];
    pv1 = g_pv[i1];
  } else { x1[0]=x1[1]=x1[2]=x1[3]=0.0f; pv1 = pv0; }
  for (int q = threadIdx.x; q < 4*32;  q += 128) sw1[q] = g_w_pe1[q];
  for (int q = threadIdx.x; q < 32*64; q += 128) sw2[q] = g_w_pe2[q];
  for (int q = threadIdx.x; q < 64*32; q += 128) sw3[q] = g_w_pe3[q];
  if (threadIdx.x < 32) { sb1[threadIdx.x] = g_b_pe1[threadIdx.x]; sb3[threadIdx.x] = g_b_pe3[threadIdx.x]; }
  if (threadIdx.x < 64) sb2[threadIdx.x] = g_b_pe2[threadIdx.x];
  __syncthreads();
  if (!act0) return;

  u64 h0[16], h1[16];
  #pragma unroll
  for (int o2 = 0; o2 < 16; o2++) { u64 b = lds2(sb1 + 2*o2); h0[o2] = b; h1[o2] = b; }
  #pragma unroll
  for (int j = 0; j < 4; j++) {
    u64 xa = bcast2(x0[j]), xb = bcast2(x1[j]);
    #pragma unroll
    for (int o4 = 0; o4 < 32; o4 += 4) {
      u64 w0, w1; ld2q(sw1 + j*32 + o4, w0, w1);
      h0[o4/2]   = fma2(xa, w0, h0[o4/2]);   h0[o4/2+1] = fma2(xa, w1, h0[o4/2+1]);
      h1[o4/2]   = fma2(xb, w0, h1[o4/2]);   h1[o4/2+1] = fma2(xb, w1, h1[o4/2+1]);
    }
  }
  #pragma unroll
  for (int o2 = 0; o2 < 16; o2++) { h0[o2] = relu2(h0[o2]); h1[o2] = relu2(h1[o2]); }

  u64 a30[16], a31[16];
  #pragma unroll
  for (int o2 = 0; o2 < 16; o2++) { u64 b = lds2(sb3 + 2*o2); a30[o2] = b; a31[o2] = b; }

  #pragma unroll
  for (int c8 = 0; c8 < 8; c8++) {
    u64 ac0[4], ac1[4];
    #pragma unroll
    for (int q = 0; q < 4; q++) { u64 b = lds2(sb2 + c8*8 + 2*q); ac0[q] = b; ac1[q] = b; }
    #pragma unroll
    for (int k2 = 0; k2 < 16; k2++) {
      float e0, e1; unpack2(h0[k2], e0, e1);
      float f0, f1; unpack2(h1[k2], f0, f1);
      {
        const float* row = sw2 + (2*k2)*64 + c8*8;
        u64 w0, w1, w2, w3; ld2q(row, w0, w1); ld2q(row + 4, w2, w3);
        u64 ea = bcast2(e0), fa = bcast2(f0);
        ac0[0] = fma2(ea, w0, ac0[0]); ac0[1] = fma2(ea, w1, ac0[1]);
        ac0[2] = fma2(ea, w2, ac0[2]); ac0[3] = fma2(ea, w3, ac0[3]);
        ac1[0] = fma2(fa, w0, ac1[0]); ac1[1] = fma2(fa, w1, ac1[1]);
        ac1[2] = fma2(fa, w2, ac1[2]); ac1[3] = fma2(fa, w3, ac1[3]);
      }
      {
        const float* row = sw2 + (2*k2+1)*64 + c8*8;
        u64 w0, w1, w2, w3; ld2q(row, w0, w1); ld2q(row + 4, w2, w3);
        u64 eb = bcast2(e1), fb = bcast2(f1);
        ac0[0] = fma2(eb, w0, ac0[0]); ac0[1] = fma2(eb, w1, ac0[1]);
        ac0[2] = fma2(eb, w2, ac0[2]); ac0[3] = fma2(eb, w3, ac0[3]);
        ac1[0] = fma2(fb, w0, ac1[0]); ac1[1] = fma2(fb, w1, ac1[1]);
        ac1[2] = fma2(fb, w2, ac1[2]); ac1[3] = fma2(fb, w3, ac1[3]);
      }
    }
    #pragma unroll
    for (int q = 0; q < 4; q++) {
      u64 hv0 = relu2(ac0[q]), hv1 = relu2(ac1[q]);
      float g0, g1; unpack2(hv0, g0, g1);
      float g2, g3; unpack2(hv1, g2, g3);
      int k = c8*8 + 2*q;
      {
        const float* row = sw3 + k*32;
        u64 ea = bcast2(g0), fa = bcast2(g2);
        #pragma unroll
        for (int o4 = 0; o4 < 32; o4 += 4) {
          u64 w0, w1; ld2q(row + o4, w0, w1);
          a30[o4/2]   = fma2(ea, w0, a30[o4/2]);   a30[o4/2+1] = fma2(ea, w1, a30[o4/2+1]);
          a31[o4/2]   = fma2(fa, w0, a31[o4/2]);   a31[o4/2+1] = fma2(fa, w1, a31[o4/2+1]);
        }
      }
      {
        const float* row = sw3 + (k+1)*32;
        u64 eb = bcast2(g1), fb = bcast2(g3);
        #pragma unroll
        for (int o4 = 0; o4 < 32; o4 += 4) {
          u64 w0, w1; ld2q(row + o4, w0, w1);
          a30[o4/2]   = fma2(eb, w0, a30[o4/2]);   a30[o4/2+1] = fma2(eb, w1, a30[o4/2+1]);
          a31[o4/2]   = fma2(fb, w0, a31[o4/2]);   a31[o4/2+1] = fma2(fb, w1, a31[o4/2+1]);
        }
      }
    }
  }

  unsigned* r0 = g_vmax + (size_t)pv0 * 32;
  unsigned* r1 = g_vmax + (size_t)pv1 * 32;
  #pragma unroll
  for (int o2 = 0; o2 < 16; o2++) {
    u64 v0 = relu2(a30[o2]);
    float lo, hi; unpack2(v0, lo, hi);
    g_pf2[(size_t)o2*N + i0] = make_float2(lo, hi);
    atomicMax(r0 + 2*o2,     __float_as_uint(lo));
    atomicMax(r0 + 2*o2 + 1, __float_as_uint(hi));
    if (act1) {
      u64 v1 = relu2(a31[o2]);
      float lo1, hi1; unpack2(v1, lo1, hi1);
      g_pf2[(size_t)o2*N + i1] = make_float2(lo1, hi1);
      atomicMax(r1 + 2*o2,     __float_as_uint(lo1));
      atomicMax(r1 + 2*o2 + 1, __float_as_uint(hi1));
    }
  }
}

// ---- per-voxel MLP + aux head, 2 voxels/thread (R8) ----
__global__ void __launch_bounds__(128, 3) k_vox(float* __restrict__ aux_out,
                                                const float* __restrict__ ax_w2, int V) {
  __shared__ __align__(16) float s1[32*32], s2[32*32], sa[32*32], sa2[32*20];
  __shared__ __align__(16) float sb1v[32], sb2v[32], sba[32];
  __shared__ float so[256*21];
  int t = blockIdx.x * 128 + threadIdx.x;
  int j0 = 2*t, j1 = j0 + 1;
  bool act0 = j0 < V, act1 = j1 < V;
  for (int q = threadIdx.x; q < 32*32; q += 128) { s1[q] = g_w_ve1[q]; s2[q] = g_w_ve2[q]; sa[q] = g_w_ax1[q]; }
  for (int q = threadIdx.x; q < 32*20; q += 128) sa2[q] = ax_w2[q];
  if (threadIdx.x < 32) { sb1v[threadIdx.x] = g_b_ve1[threadIdx.x]; sb2v[threadIdx.x] = g_b_ve2[threadIdx.x]; sba[threadIdx.x] = g_b_ax1[threadIdx.x]; }
  __syncthreads();
  if (act0) {
    int jj1 = act1 ? j1 : j0;
    u64 v10[16], v11[16];
    #pragma unroll
    for (int o2 = 0; o2 < 16; o2++) { u64 b = lds2(sb1v + 2*o2); v10[o2] = b; v11[o2] = b; }
    const uint4* vr0 = reinterpret_cast<const uint4*>(g_vmax + (size_t)j0 * 32);
    const uint4* vr1 = reinterpret_cast<const uint4*>(g_vmax + (size_t)jj1 * 32);
    #pragma unroll
    for (int q = 0; q < 8; q++) {
      uint4 A = vr0[q], B = vr1[q];
      float a4[4] = { __uint_as_float(A.x), __uint_as_float(A.y), __uint_as_float(A.z), __uint_as_float(A.w) };
      float b4[4] = { __uint_as_float(B.x), __uint_as_float(B.y), __uint_as_float(B.z), __uint_as_float(B.w) };
      #pragma unroll
      for (int jj = 0; jj < 4; jj++) {
        u64 ea = bcast2(a4[jj]), fb = bcast2(b4[jj]);
        const float* row = s1 + (q*4 + jj)*32;
        #pragma unroll
        for (int o4 = 0; o4 < 32; o4 += 4) {
          u64 w0, w1; ld2q(row + o4, w0, w1);
          v10[o4/2] = fma2(ea, w0, v10[o4/2]); v10[o4/2+1] = fma2(ea, w1, v10[o4/2+1]);
          v11[o4/2] = fma2(fb, w0, v11[o4/2]); v11[o4/2+1] = fma2(fb, w1, v11[o4/2+1]);
        }
      }
    }
    #pragma unroll
    for (int o2 = 0; o2 < 16; o2++) { v10[o2] = relu2(v10[o2]); v11[o2] = relu2(v11[o2]); }
    {
      u64 vf0[16], vf1[16];
      #pragma unroll
      for (int o2 = 0; o2 < 16; o2++) { u64 b = lds2(sb2v + 2*o2); vf0[o2] = b; vf1[o2] = b; }
      #pragma unroll
      for (int k2 = 0; k2 < 16; k2++) {
        float e0, e1; unpack2(v10[k2], e0, e1);
        float f0, f1; unpack2(v11[k2], f0, f1);
        {
          const float* row = s2 + (2*k2)*32;
          u64 ea = bcast2(e0), fa = bcast2(f0);
          #pragma unroll
          for (int o4 = 0; o4 < 32; o4 += 4) {
            u64 w0, w1; ld2q(row + o4, w0, w1);
            vf0[o4/2] = fma2(ea, w0, vf0[o4/2]); vf0[o4/2+1] = fma2(ea, w1, vf0[o4/2+1]);
            vf1[o4/2] = fma2(fa, w0, vf1[o4/2]); vf1[o4/2+1] = fma2(fa, w1, vf1[o4/2+1]);
          }
        }
        {
          const float* row = s2 + (2*k2+1)*32;
          u64 eb = bcast2(e1), fb = bcast2(f1);
          #pragma unroll
          for (int o4 = 0; o4 < 32; o4 += 4) {
            u64 w0, w1; ld2q(row + o4, w0, w1);
            vf0[o4/2] = fma2(eb, w0, vf0[o4/2]); vf0[o4/2+1] = fma2(eb, w1, vf0[o4/2+1]);
            vf1[o4/2] = fma2(fb, w0, vf1[o4/2]); vf1[o4/2+1] = fma2(fb, w1, vf1[o4/2+1]);
          }
        }
      }
      float* vfr0 = g_vf + (size_t)j0 * 32;
      float* vfr1 = g_vf + (size_t)jj1 * 32;
      #pragma unroll
      for (int o2 = 0; o2 < 16; o2++) {
        u64 v = relu2(vf0[o2]);
        float lo, hi; unpack2(v, lo, hi);
        *reinterpret_cast<float2*>(vfr0 + 2*o2) = make_float2(lo, hi);
        if (act1) {
          v = relu2(vf1[o2]);
          unpack2(v, lo, hi);
          *reinterpret_cast<float2*>(vfr1 + 2*o2) = make_float2(lo, hi);
        }
      }
    }
    {
      u64 ah0[16], ah1[16];
      #pragma unroll
      for (int o2 = 0; o2 < 16; o2++) { u64 b = lds2(sba + 2*o2); ah0[o2] = b; ah1[o2] = b; }
      #pragma unroll
      for (int k2 = 0; k2 < 16; k2++) {
        float e0, e1; unpack2(v10[k2], e0, e1);
        float f0, f1; unpack2(v11[k2], f0, f1);
        {
          const float* row = sa + (2*k2)*32;
          u64 ea = bcast2(e0), fa = bcast2(f0);
          #pragma unroll
          for (int o4 = 0; o4 < 32; o4 += 4) {
            u64 w0, w1; ld2q(row + o4, w0, w1);
            ah0[o4/2] = fma2(ea, w0, ah0[o4/2]); ah0[o4/2+1] = fma2(ea, w1, ah0[o4/2+1]);
            ah1[o4/2] = fma2(fa, w0, ah1[o4/2]); ah1[o4/2+1] = fma2(fa, w1, ah1[o4/2+1]);
          }
        }
        {
          const float* row = sa + (2*k2+1)*32;
          u64 eb = bcast2(e1), fb = bcast2(f1);
          #pragma unroll
          for (int o4 = 0; o4 < 32; o4 += 4) {
            u64 w0, w1; ld2q(row + o4, w0, w1);
            ah0[o4/2] = fma2(eb, w0, ah0[o4/2]); ah0[o4/2+1] = fma2(eb, w1, ah0[o4/2+1]);
            ah1[o4/2] = fma2(fb, w0, ah1[o4/2]); ah1[o4/2+1] = fma2(fb, w1, ah1[o4/2+1]);
          }
        }
      }
      u64 ac0[10], ac1[10];
      #pragma unroll
      for (int o2 = 0; o2 < 10; o2++) { ac0[o2] = 0; ac1[o2] = 0; }
      #pragma unroll
      for (int k2 = 0; k2 < 16; k2++) {
        u64 hv0 = relu2(ah0[k2]), hv1 = relu2(ah1[k2]);
        float e0, e1; unpack2(hv0, e0, e1);
        float f0, f1; unpack2(hv1, f0, f1);
        {
          const float* row = sa2 + (2*k2)*20;
          u64 ea = bcast2(e0), fa = bcast2(f0);
          #pragma unroll
          for (int o2 = 0; o2 < 10; o2++) {
            u64 w = lds2(row + 2*o2);
            ac0[o2] = fma2(ea, w, ac0[o2]); ac1[o2] = fma2(fa, w, ac1[o2]);
          }
        }
        {
          const float* row = sa2 + (2*k2+1)*20;
          u64 eb = bcast2(e1), fb = bcast2(f1);
          #pragma unroll
          for (int o2 = 0; o2 < 10; o2++) {
            u64 w = lds2(row + 2*o2);
            ac0[o2] = fma2(eb, w, ac0[o2]); ac1[o2] = fma2(fb, w, ac1[o2]);
          }
        }
      }
      int r0 = 2*threadIdx.x, r1 = r0 + 1;
      #pragma unroll
      for (int o2 = 0; o2 < 10; o2++) {
        float lo, hi; unpack2(ac0[o2], lo, hi);
        so[r0*21 + 2*o2] = lo; so[r0*21 + 2*o2 + 1] = hi;
        unpack2(ac1[o2], lo, hi);
        so[r1*21 + 2*o2] = lo; so[r1*21 + 2*o2 + 1] = hi;
      }
    }
  }
  __syncthreads();
  int base = blockIdx.x * 256;
  int rows = V - base; if (rows > 256) rows = 256;
  if (rows > 0)
    for (int q = threadIdx.x; q < rows*20; q += 128)
      aux_out[(size_t)base*20 + q] = so[(q/20)*21 + (q%20)];
}

// ---- fuse 64->64 via mma.sync bf16 hi/lo; 128 points/CTA (R14 winner) ----
__global__ void __launch_bounds__(128) k_fuse(const float* __restrict__ points, int N) {
  extern __shared__ unsigned pool[];
  unsigned* sAh = pool;
  unsigned* sAl = pool + 4352;
  unsigned* sBh = pool + 8704;
  unsigned* sBl = pool + 11008;
  __shared__ float sbias[64];
  __shared__ float swsum[4][64];
  __shared__ int   swb[4];

  int tid = threadIdx.x;
  int lane = tid & 31, wid = tid >> 5;
  int i = blockIdx.x * 128 + tid;
  bool act = i < N;
  int b = -1, pv = 0;
  if (act) { pv = g_pv[i]; b = (int)points[(size_t)i*5]; }

  float in[64];
  if (act) {
    const float4* vr = reinterpret_cast<const float4*>(g_vf + (size_t)pv * 32);
    #pragma unroll
    for (int q = 0; q < 8; q++) {
      float4 A = vr[q];
      in[4*q]=A.x; in[4*q+1]=A.y; in[4*q+2]=A.z; in[4*q+3]=A.w;
    }
    #pragma unroll
    for (int c2 = 0; c2 < 16; c2++) {
      float2 v = g_pf2[(size_t)c2*N + i];
      in[32+2*c2] = v.x; in[32+2*c2+1] = v.y;
    }
  } else {
    #pragma unroll
    for (int c = 0; c < 64; c++) in[c] = 0.0f;
  }

  for (int q = tid; q < 64*32; q += 128) {
    int n = q >> 5, kp = q & 31;
    sBh[n*36 + kp] = g_fu_bh2[q];
    sBl[n*36 + kp] = g_fu_bl2[q];
  }
  if (tid < 64) sbias[tid] = g_b_fu[tid];

  #pragma unroll
  for (int kp = 0; kp < 32; kp++) {
    float x0 = in[2*kp], x1 = in[2*kp+1];
    __nv_bfloat16 h0 = __float2bfloat16_rn(x0), h1 = __float2bfloat16_rn(x1);
    float l0 = x0 - __bfloat162float(h0), l1 = x1 - __bfloat162float(h1);
    sAh[kp*136 + tid] = ((unsigned)__bfloat16_as_ushort(h1) << 16) | __bfloat16_as_ushort(h0);
    sAl[kp*136 + tid] = ((unsigned)__bfloat16_as_ushort(__float2bfloat16_rn(l1)) << 16)
                      | __bfloat16_as_ushort(__float2bfloat16_rn(l0));
  }
  __syncthreads();

  int g = lane >> 2, tig = lane & 3;
  float d[2][8][4];
  #pragma unroll
  for (int mt = 0; mt < 2; mt++)
    #pragma unroll
    for (int nt = 0; nt < 8; nt++)
      #pragma unroll
      for (int q = 0; q < 4; q++) d[mt][nt][q] = 0.0f;

  #pragma unroll
  for (int term = 0; term < 3; term++) {
    const unsigned* A = (term == 2) ? sAl : sAh;
    const unsigned* B = (term == 1) ? sBl : sBh;
    #pragma unroll
    for (int ks = 0; ks < 4; ks++) {
      unsigned a[2][4];
      #pragma unroll
      for (int mt = 0; mt < 2; mt++) {
        int r0 = wid*32 + mt*16 + g;
        a[mt][0] = A[(ks*8 + tig)*136 + r0];
        a[mt][1] = A[(ks*8 + tig)*136 + r0 + 8];
        a[mt][2] = A[(ks*8 + 4 + tig)*136 + r0];
        a[mt][3] = A[(ks*8 + 4 + tig)*136 + r0 + 8];
      }
      #pragma unroll
      for (int nt = 0; nt < 8; nt++) {
        int n = nt*8 + g;
        unsigned b0 = B[n*36 + ks*8 + tig];
        unsigned b1 = B[n*36 + ks*8 + 4 + tig];
        mma16816(d[0][nt], a[0], b0, b1);
        mma16816(d[1][nt], a[1], b0, b1);
      }
    }
  }
  __syncthreads();

  float* sD = reinterpret_cast<float*>(pool);
  #pragma unroll
  for (int mt = 0; mt < 2; mt++) {
    int r0 = wid*32 + mt*16 + g;
    #pragma unroll
    for (int nt = 0; nt < 8; nt++) {
      int c = nt*8 + tig*2;
      sD[r0*65 + c]       = d[mt][nt][0];
      sD[r0*65 + c + 1]   = d[mt][nt][1];
      sD[(r0+8)*65 + c]   = d[mt][nt][2];
      sD[(r0+8)*65 + c+1] = d[mt][nt][3];
    }
  }
  __syncthreads();

  float dv[64];
  #pragma unroll
  for (int c = 0; c < 64; c++)
    dv[c] = act ? fmaxf(sD[tid*65 + c] + sbias[c], 0.0f) : 0.0f;
  if (act) {
    #pragma unroll
    for (int c2 = 0; c2 < 32; c2++)
      g_fused2[(size_t)c2*N + i] = make_float2(dv[2*c2], dv[2*c2+1]);
  }
  bool fast = (__match_any_sync(FULLM, b) == FULLM) && __all_sync(FULLM, b >= 0);
  if (lane == 0) swb[wid] = fast ? b : -1;
  if (fast) {
    #pragma unroll
    for (int c2 = 0; c2 < 32; c2++) {
      u64 v = pack2(dv[2*c2], dv[2*c2+1]);
      v = add2(v, __shfl_xor_sync(FULLM, v, 16));
      v = add2(v, __shfl_xor_sync(FULLM, v, 8));
      v = add2(v, __shfl_xor_sync(FULLM, v, 4));
      v = add2(v, __shfl_xor_sync(FULLM, v, 2));
      v = add2(v, __shfl_xor_sync(FULLM, v, 1));
      if (lane == 0) {
        float sl, sh; unpack2(v, sl, sh);
        swsum[wid][2*c2] = sl; swsum[wid][2*c2+1] = sh;
      }
    }
  } else if (act) {
    for (int c = 0; c < 64; c++) atomicAdd(&g_bsum[b*64 + c], dv[c]);
    atomicAdd(&g_bcnt[b], 1u);
  }
  __syncthreads();
  if (tid < 64) {
    int c = tid;
    int curb = -1; float cv = 0.0f;
    for (int w = 0; w < 4; w++) {
      int wb = swb[w];
      if (wb < 0) continue;
      if (wb != curb) { if (curb >= 0) atomicAdd(&g_bsum[curb*64 + c], cv); curb = wb; cv = 0.0f; }
      cv += swsum[w][c];
    }
    if (curb >= 0) atomicAdd(&g_bsum[curb*64 + c], cv);
  }
  if (tid == 0) {
    int curb = -1; unsigned cc = 0;
    for (int w = 0; w < 4; w++) {
      int wb = swb[w];
      if (wb < 0) continue;
      if (wb != curb) { if (curb >= 0) atomicAdd(&g_bcnt[curb], cc); curb = wb; cc = 0; }
      cc += 32;
    }
    if (curb >= 0) atomicAdd(&g_bcnt[curb], cc);
  }
}

// ---- SE gate ----
__global__ void k_se(const float* __restrict__ se_w1, const float* __restrict__ se_b1,
                     const float* __restrict__ se_w2, const float* __restrict__ se_b2) {
  __shared__ float mean[4*64], t1[16];
  int tid = threadIdx.x;
  int b = tid >> 6, c = tid & 63;
  mean[tid] = g_bsum[tid] / fmaxf((float)g_bcnt[b], 1.0f);
  __syncthreads();
  if (tid < 16) {
    int bb = tid >> 2, jj = tid & 3;
    float a = se_b1[jj];
    for (int k = 0; k < 64; k++) a += mean[bb*64 + k] * se_w1[k*4 + jj];
    t1[tid] = fmaxf(a, 0.0f);
  }
  __syncthreads();
  {
    float a = se_b2[c];
    #pragma unroll
    for (int jj = 0; jj < 4; jj++) a += t1[b*4 + jj] * se_w2[jj*64 + c];
    g_gp1[tid] = 1.0f + 1.0f / (1.0f + expf(-a));
  }
}

// ---- classifier head via mma.sync: gate, 64->32 (mma), relu, 32->20 (scalar) ----
__global__ void __launch_bounds__(128) k_out(const float* __restrict__ points,
                                             const float* __restrict__ cl_w2,
                                             float* __restrict__ out, int N) {
  extern __shared__ unsigned pool[];
  unsigned* sAh = pool;           // [kp][row] stride 136: 4352
  unsigned* sAl = pool + 4352;    // 4352
  unsigned* sBh = pool + 8704;    // [n][kp] stride 36, n<32: 1152
  unsigned* sBl = pool + 9856;    // 1152 → 11008 u32 total
  __shared__ __align__(16) float sw2[32*20], sb1c[32];
  __shared__ __align__(8) float sg[256];
  __shared__ float so[128*21];

  int tid = threadIdx.x;
  int lane = tid & 31, wid = tid >> 5;
  int i = blockIdx.x * 128 + tid;
  bool act = i < N;
  int b = 0;
  if (act) b = (int)points[(size_t)i*5];

  for (int q = tid; q < 32*32; q += 128) {
    int n = q >> 5, kp = q & 31;
    sBh[n*36 + kp] = g_cl_bh2[q];
    sBl[n*36 + kp] = g_cl_bl2[q];
  }
  for (int q = tid; q < 32*20; q += 128) sw2[q] = cl_w2[q];
  if (tid < 32) sb1c[tid] = g_b_cl1[tid];
  for (int q = tid; q < 256; q += 128) sg[q] = g_gp1[q];
  __syncthreads();

  // gather fused, apply gate in fp32, split hi/lo into sA
  {
    const float* gb = sg + b*64;
    #pragma unroll
    for (int kp = 0; kp < 32; kp++) {
      float x0 = 0.0f, x1 = 0.0f;
      if (act) {
        float2 fv = g_fused2[(size_t)kp*N + i];
        float2 gv = *reinterpret_cast<const float2*>(gb + 2*kp);
        x0 = fv.x * gv.x; x1 = fv.y * gv.y;
      }
      __nv_bfloat16 h0 = __float2bfloat16_rn(x0), h1 = __float2bfloat16_rn(x1);
      float l0 = x0 - __bfloat162float(h0), l1 = x1 - __bfloat162float(h1);
      sAh[kp*136 + tid] = ((unsigned)__bfloat16_as_ushort(h1) << 16) | __bfloat16_as_ushort(h0);
      sAl[kp*136 + tid] = ((unsigned)__bfloat16_as_ushort(__float2bfloat16_rn(l1)) << 16)
                        | __bfloat16_as_ushort(__float2bfloat16_rn(l0));
    }
  }
  __syncthreads();

  int g = lane >> 2, tig = lane & 3;
  float d[2][4][4];
  #pragma unroll
  for (int mt = 0; mt < 2; mt++)
    #pragma unroll
    for (int nt = 0; nt < 4; nt++)
      #pragma unroll
      for (int q = 0; q < 4; q++) d[mt][nt][q] = 0.0f;

  #pragma unroll
  for (int term = 0; term < 3; term++) {
    const unsigned* A = (term == 2) ? sAl : sAh;
    const unsigned* B = (term == 1) ? sBl : sBh;
    #pragma unroll
    for (int ks = 0; ks < 4; ks++) {
      unsigned a[2][4];
      #pragma unroll
      for (int mt = 0; mt < 2; mt++) {
        int r0 = wid*32 + mt*16 + g;
        a[mt][0] = A[(ks*8 + tig)*136 + r0];
        a[mt][1] = A[(ks*8 + tig)*136 + r0 + 8];
        a[mt][2] = A[(ks*8 + 4 + tig)*136 + r0];
        a[mt][3] = A[(ks*8 + 4 + tig)*136 + r0 + 8];
      }
      #pragma unroll
      for (int nt = 0; nt < 4; nt++) {
        int n = nt*8 + g;
        unsigned b0 = B[n*36 + ks*8 + tig];
        unsigned b1 = B[n*36 + ks*8 + 4 + tig];
        mma16816(d[0][nt], a[0], b0, b1);
        mma16816(d[1][nt], a[1], b0, b1);
      }
    }
  }
  __syncthreads();

  // stage D [row][c] stride 34 (reuses sAh region: 128*34 = 4352)
  float* sD = reinterpret_cast<float*>(pool);
  #pragma unroll
  for (int mt = 0; mt < 2; mt++) {
    int r0 = wid*32 + mt*16 + g;
    #pragma unroll
    for (int nt = 0; nt < 4; nt++) {
      int c = nt*8 + tig*2;
      sD[r0*34 + c]       = d[mt][nt][0];
      sD[r0*34 + c + 1]   = d[mt][nt][1];
      sD[(r0+8)*34 + c]   = d[mt][nt][2];
      sD[(r0+8)*34 + c+1] = d[mt][nt][3];
    }
  }
  __syncthreads();

  if (act) {
    // bias + relu into packed pairs
    u64 h[16];
    #pragma unroll
    for (int k2 = 0; k2 < 16; k2++)
      h[k2] = relu2(add2(lds2(sD + tid*34 + 2*k2), lds2(sb1c + 2*k2)));
    // head 32->20
    u64 acc[10];
    #pragma unroll
    for (int q = 0; q < 10; q++) acc[q] = 0;
    #pragma unroll
    for (int k2 = 0; k2 < 16; k2++) {
      float e0, e1; unpack2(h[k2], e0, e1);
      {
        const float* row = sw2 + (2*k2)*20;
        u64 ea = bcast2(e0);
        #pragma unroll
        for (int q = 0; q < 10; q++) acc[q] = fma2(ea, lds2(row + 2*q), acc[q]);
      }
      {
        const float* row = sw2 + (2*k2+1)*20;
        u64 eb = bcast2(e1);
        #pragma unroll
        for (int q = 0; q < 10; q++) acc[q] = fma2(eb, lds2(row + 2*q), acc[q]);
      }
    }
    #pragma unroll
    for (int q = 0; q < 10; q++) {
      float lo, hi; unpack2(acc[q], lo, hi);
      so[tid*21 + 2*q] = lo; so[tid*21 + 2*q + 1] = hi;
    }
  }
  __syncthreads();
  int base = blockIdx.x * 128;
  int rows = N - base; if (rows > 128) rows = 128;
  if (rows > 0)
    for (int q = tid; q < rows*20; q += 128)
      out[(size_t)base*20 + q] = so[(q/20)*21 + (q%20)];
}

extern "C" void kernel_launch(void* const* d_in, const int* in_sizes, int n_in,
                              void* d_out, int out_size) {
  const float* points = (const float*)d_in[0];
  int N = in_sizes[0] / 5;
  int V = (out_size - N * 20) / 20;
  float* out = (float*)d_out;
  float* aux_out = out + (size_t)N * 20;

  WP wp;
  wp.pe_w1 = (const float*)d_in[2];  wp.pe_g1 = (const float*)d_in[3];  wp.pe_b1 = (const float*)d_in[4];
  wp.pe_w2 = (const float*)d_in[5];  wp.pe_g2 = (const float*)d_in[6];  wp.pe_b2 = (const float*)d_in[7];
  wp.pe_w3 = (const float*)d_in[8];  wp.pe_g3 = (const float*)d_in[9];  wp.pe_b3 = (const float*)d_in[10];
  wp.ve_w1 = (const float*)d_in[11]; wp.ve_g1 = (const float*)d_in[12]; wp.ve_b1 = (const float*)d_in[13];
  wp.ve_w2 = (const float*)d_in[14]; wp.ve_g2 = (const float*)d_in[15]; wp.ve_b2 = (const float*)d_in[16];
  wp.fu_w  = (const float*)d_in[17]; wp.fu_g  = (const float*)d_in[18]; wp.fu_b  = (const float*)d_in[19];
  wp.cl_w1 = (const float*)d_in[24]; wp.cl_g1 = (const float*)d_in[25]; wp.cl_b1 = (const float*)d_in[26];
  wp.ax_w1 = (const float*)d_in[28]; wp.ax_g1 = (const float*)d_in[29]; wp.ax_b1 = (const float*)d_in[30];
  wp.pv_raw = (const int*)d_in[1];

  static int smem_set = 0;
  if (!smem_set) {
    cudaFuncSetAttribute(k_fuse, cudaFuncAttributeMaxDynamicSharedMemorySize, 13312*4);
    cudaFuncSetAttribute(k_out,  cudaFuncAttributeMaxDynamicSharedMemorySize, 11008*4);
    smem_set = 1;
  }

  k_prep<<<1, 256>>>(wp);

  int tot = 32 * V; if (N > tot) tot = N;
  k_init<<<(tot + 255) / 256, 256>>>(d_in[1], N, V);

  k_points<<<(N + 255) / 256, 128>>>(points, N);
  k_vox<<<(V + 255) / 256, 128>>>(aux_out, (const float*)d_in[31], V);
  k_fuse<<<(N + 127) / 128, 128, 13312*4>>>(points, N);
  k_se<<<1, 256>>>((const float*)d_in[20], (const float*)d_in[21],
                   (const float*)d_in[22], (const float*)d_in[23]);
  k_out<<<(N + 127) / 128, 128, 11008*4>>>(points, (const float*)d_in[27], out, N);
}

// round 17
// speedup vs baseline: 1.1549x; 1.1549x over previous
#include <cuda_runtime.h>
#include <cuda_bf16.h>

typedef unsigned long long u64;
#define FULLM 0xffffffffu
#define NMAXP 1000000
#define VMAXP 200000

// ---- packed f32x2 helpers ----
__device__ __forceinline__ u64 pack2(float a, float b) {
  u64 r;
  asm("mov.b64 %0, {%1, %2};" : "=l"(r) : "r"(__float_as_uint(a)), "r"(__float_as_uint(b)));
  return r;
}
__device__ __forceinline__ void unpack2(u64 v, float& a, float& b) {
  unsigned x, y;
  asm("mov.b64 {%0, %1}, %2;" : "=r"(x), "=r"(y) : "l"(v));
  a = __uint_as_float(x); b = __uint_as_float(y);
}
__device__ __forceinline__ u64 bcast2(float v) { return pack2(v, v); }
__device__ __forceinline__ u64 fma2(u64 a, u64 b, u64 c) {
  u64 r; asm("fma.rn.f32x2 %0, %1, %2, %3;" : "=l"(r) : "l"(a), "l"(b), "l"(c)); return r;
}
__device__ __forceinline__ u64 add2(u64 a, u64 b) {
  u64 r; asm("add.rn.f32x2 %0, %1, %2;" : "=l"(r) : "l"(a), "l"(b)); return r;
}
__device__ __forceinline__ u64 relu2(u64 v) {
  float a, b; unpack2(v, a, b);
  return pack2(fmaxf(a, 0.0f), fmaxf(b, 0.0f));
}
__device__ __forceinline__ u64 lds2(const float* p) {
  float2 v = *reinterpret_cast<const float2*>(p); return pack2(v.x, v.y);
}
__device__ __forceinline__ void ld2q(const float* p, u64& w0, u64& w1) {
  float4 v = *reinterpret_cast<const float4*>(p);
  w0 = pack2(v.x, v.y); w1 = pack2(v.z, v.w);
}

// ---- legacy tensor-core mma (works on bare sm_103) ----
__device__ __forceinline__ void mma16816(float* d, const unsigned* a, unsigned b0, unsigned b1) {
  asm volatile(
      "mma.sync.aligned.m16n8k16.row.col.f32.bf16.bf16.f32 "
      "{%0,%1,%2,%3}, {%4,%5,%6,%7}, {%8,%9}, {%0,%1,%2,%3};"
      : "+f"(d[0]), "+f"(d[1]), "+f"(d[2]), "+f"(d[3])
      : "r"(a[0]), "r"(a[1]), "r"(a[2]), "r"(a[3]), "r"(b0), "r"(b1));
}
__device__ __forceinline__ void bfsplit(float x, unsigned short& h, unsigned short& l) {
  __nv_bfloat16 hb = __float2bfloat16_rn(x);
  h = __bfloat16_as_ushort(hb);
  l = __bfloat16_as_ushort(__float2bfloat16_rn(x - __bfloat162float(hb)));
}

struct WP {
  const float *pe_w1,*pe_g1,*pe_b1,*pe_w2,*pe_g2,*pe_b2,*pe_w3,*pe_g3,*pe_b3;
  const float *ve_w1,*ve_g1,*ve_b1,*ve_w2,*ve_g2,*ve_b2;
  const float *fu_w,*fu_g,*fu_b;
  const float *cl_w1,*cl_g1,*cl_b1;
  const float *ax_w1,*ax_g1,*ax_b1;
  const int   *pv_raw;
};

// ---- folded weights ----
static __device__ float g_w_pe1[4*32],  g_b_pe1[32];
static __device__ float g_w_pe2[32*64], g_b_pe2[64];
static __device__ float g_w_pe3[64*32], g_b_pe3[32];
static __device__ float g_w_ve1[32*32], g_b_ve1[32];
static __device__ float g_w_ve2[32*32], g_b_ve2[32];
static __device__ float g_w_fu [64*64], g_b_fu [64];
static __device__ float g_w_cl1[64*32], g_b_cl1[32];
static __device__ float g_w_ax1[32*32], g_b_ax1[32];
// bf16 hi/lo n-major k-pair packs
static __device__ unsigned g_fu_bh2[64*32],  g_fu_bl2[64*32];
static __device__ unsigned g_pe2_bh2[64*16], g_pe2_bl2[64*16];
static __device__ unsigned g_pe3_bh2[32*32], g_pe3_bl2[32*32];

// ---- scratch ----
static __device__ int      g_pv_is64;
static __device__ int      g_pv[NMAXP];
static __device__ float2   g_pf2[16*NMAXP];
static __device__ unsigned g_vmax[VMAXP*32];
static __device__ float    g_vf[VMAXP*32];
static __device__ float2   g_fused2[32*NMAXP];
static __device__ float    g_bsum[4*64];
static __device__ unsigned g_bcnt[4];
static __device__ float    g_gp1[4*64];

__device__ __forceinline__ void fold_w(float* dw, float* db,
    const float* W, const float* g, const float* b, int fi, int fo) {
  const float inv = 1.0f / sqrtf(1.0f + 1e-5f);
  for (int t = threadIdx.x; t < fi*fo; t += blockDim.x) dw[t] = W[t] * (g[t % fo] * inv);
  for (int t = threadIdx.x; t < fo;    t += blockDim.x) db[t] = b[t];
}
__device__ __forceinline__ void pack_nmajor(unsigned* bh, unsigned* bl,
    const float* W, int fo, int kpairs) {
  for (int t = threadIdx.x; t < fo*kpairs; t += blockDim.x) {
    int n = t / kpairs, kp = t % kpairs;
    float w0 = W[(2*kp)*fo + n], w1 = W[(2*kp+1)*fo + n];
    unsigned short h0, l0, h1, l1;
    bfsplit(w0, h0, l0); bfsplit(w1, h1, l1);
    bh[t] = ((unsigned)h1 << 16) | h0;
    bl[t] = ((unsigned)l1 << 16) | l0;
  }
}

__global__ void k_prep(WP p) {
  fold_w(g_w_pe1, g_b_pe1, p.pe_w1, p.pe_g1, p.pe_b1, 4, 32);
  fold_w(g_w_pe2, g_b_pe2, p.pe_w2, p.pe_g2, p.pe_b2, 32, 64);
  fold_w(g_w_pe3, g_b_pe3, p.pe_w3, p.pe_g3, p.pe_b3, 64, 32);
  fold_w(g_w_ve1, g_b_ve1, p.ve_w1, p.ve_g1, p.ve_b1, 32, 32);
  fold_w(g_w_ve2, g_b_ve2, p.ve_w2, p.ve_g2, p.ve_b2, 32, 32);
  fold_w(g_w_fu,  g_b_fu,  p.fu_w,  p.fu_g,  p.fu_b,  64, 64);
  fold_w(g_w_cl1, g_b_cl1, p.cl_w1, p.cl_g1, p.cl_b1, 64, 32);
  fold_w(g_w_ax1, g_b_ax1, p.ax_w1, p.ax_g1, p.ax_b1, 32, 32);
  __syncthreads();
  pack_nmajor(g_fu_bh2,  g_fu_bl2,  g_w_fu,  64, 32);
  pack_nmajor(g_pe2_bh2, g_pe2_bl2, g_w_pe2, 64, 16);
  pack_nmajor(g_pe3_bh2, g_pe3_bl2, g_w_pe3, 32, 32);
  if (threadIdx.x == 0) {
    int z = 1;
    for (int k = 1; k < 128; k += 2) if (p.pv_raw[k] != 0) { z = 0; break; }
    g_pv_is64 = z;
  }
}

__global__ void k_init(const void* pv_raw, int N, int V) {
  int i = blockIdx.x * blockDim.x + threadIdx.x;
  if (i < N) {
    g_pv[i] = g_pv_is64 ? (int)((const long long*)pv_raw)[i]
                        : ((const int*)pv_raw)[i];
  }
  if (i < 32*V) g_vmax[i] = 0u;
  if (i < 256)  g_bsum[i] = 0.0f;
  if (i < 4)    g_bcnt[i] = 0u;
}

// ---- per-point MLP via mma: L1 scalar, L2/L3 tensor, reg-resident interlayer ----
__global__ void __launch_bounds__(128) k_points(const float* __restrict__ points, int N) {
  extern __shared__ unsigned pool[];
  unsigned* sA1h = pool;           // [kp16][row] stride 136 = 2176
  unsigned* sA1l = pool + 2176;    // 2176
  unsigned* sW2h = pool + 4352;    // [n64][kp16] stride 20 = 1280
  unsigned* sW2l = pool + 5632;    // 1280
  unsigned* sW3h = pool + 6912;    // [n32][kp32] stride 36 = 1152
  unsigned* sW3l = pool + 8064;    // 1152  (total 9216 u32; D2 stage 128*34=4352 reuses sA1)
  __shared__ __align__(16) float sw1[4*32], sb1[32], sb2[64], sb3[32];

  int tid = threadIdx.x;
  int lane = tid & 31, wid = tid >> 5;
  int i = blockIdx.x * 128 + tid;
  bool act = i < N;
  int pv = 0;
  float x[4] = {0.f, 0.f, 0.f, 0.f};
  if (act) {
    const float* p = points + (size_t)i * 5;
    x[0]=p[1]; x[1]=p[2]; x[2]=p[3]; x[3]=p[4];
    pv = g_pv[i];
  }
  for (int q = tid; q < 4*32; q += 128) sw1[q] = g_w_pe1[q];
  if (tid < 32) { sb1[tid] = g_b_pe1[tid]; sb3[tid] = g_b_pe3[tid]; }
  if (tid < 64) sb2[tid] = g_b_pe2[tid];
  for (int q = tid; q < 64*16; q += 128) {
    int n = q >> 4, kp = q & 15;
    sW2h[n*20 + kp] = g_pe2_bh2[q];
    sW2l[n*20 + kp] = g_pe2_bl2[q];
  }
  for (int q = tid; q < 32*32; q += 128) {
    int n = q >> 5, kp = q & 31;
    sW3h[n*36 + kp] = g_pe3_bh2[q];
    sW3l[n*36 + kp] = g_pe3_bl2[q];
  }
  __syncthreads();

  // L1: 4->32 scalar, split hi/lo into sA1
  #pragma unroll
  for (int kp = 0; kp < 16; kp++) {
    float a0 = sb1[2*kp], a1 = sb1[2*kp+1];
    #pragma unroll
    for (int j = 0; j < 4; j++) {
      a0 += x[j] * sw1[j*32 + 2*kp];
      a1 += x[j] * sw1[j*32 + 2*kp + 1];
    }
    a0 = act ? fmaxf(a0, 0.0f) : 0.0f;
    a1 = act ? fmaxf(a1, 0.0f) : 0.0f;
    unsigned short h0, l0, h1, l1;
    bfsplit(a0, h0, l0); bfsplit(a1, h1, l1);
    sA1h[kp*136 + tid] = ((unsigned)h1 << 16) | h0;
    sA1l[kp*136 + tid] = ((unsigned)l1 << 16) | l0;
  }
  __syncthreads();

  int g = lane >> 2, tig = lane & 3;

  // L2 mma: D1[128x64] = A1[128x32] * W2[32x64]
  float d1[2][8][4];
  #pragma unroll
  for (int mt = 0; mt < 2; mt++)
    #pragma unroll
    for (int nt = 0; nt < 8; nt++)
      #pragma unroll
      for (int q = 0; q < 4; q++) d1[mt][nt][q] = 0.0f;
  #pragma unroll
  for (int term = 0; term < 3; term++) {
    const unsigned* A = (term == 2) ? sA1l : sA1h;
    const unsigned* B = (term == 1) ? sW2l : sW2h;
    #pragma unroll
    for (int ks = 0; ks < 2; ks++) {
      unsigned a[2][4];
      #pragma unroll
      for (int mt = 0; mt < 2; mt++) {
        int r0 = wid*32 + mt*16 + g;
        a[mt][0] = A[(ks*8 + tig)*136 + r0];
        a[mt][1] = A[(ks*8 + tig)*136 + r0 + 8];
        a[mt][2] = A[(ks*8 + 4 + tig)*136 + r0];
        a[mt][3] = A[(ks*8 + 4 + tig)*136 + r0 + 8];
      }
      #pragma unroll
      for (int nt = 0; nt < 8; nt++) {
        int n = nt*8 + g;
        unsigned b0 = B[n*20 + ks*8 + tig];
        unsigned b1 = B[n*20 + ks*8 + 4 + tig];
        mma16816(d1[0][nt], a[0], b0, b1);
        mma16816(d1[1][nt], a[1], b0, b1);
      }
    }
  }
  __syncthreads();   // sA1 reads done; region reusable

  // bias+relu on d1, split hi/lo into register A2 fragments
  unsigned a2h[2][4][4], a2l[2][4][4];
  #pragma unroll
  for (int mt = 0; mt < 2; mt++) {
    #pragma unroll
    for (int nt = 0; nt < 8; nt++) {
      int c = nt*8 + 2*tig;
      float b0v = sb2[c], b1v = sb2[c+1];
      float v0 = fmaxf(d1[mt][nt][0] + b0v, 0.0f);
      float v1 = fmaxf(d1[mt][nt][1] + b1v, 0.0f);
      float v2 = fmaxf(d1[mt][nt][2] + b0v, 0.0f);
      float v3 = fmaxf(d1[mt][nt][3] + b1v, 0.0f);
      unsigned short h0,l0,h1,l1,h2,l2,h3,l3;
      bfsplit(v0,h0,l0); bfsplit(v1,h1,l1); bfsplit(v2,h2,l2); bfsplit(v3,h3,l3);
      int ks2 = nt >> 1, sub = (nt & 1) ? 2 : 0;
      a2h[mt][ks2][sub]   = ((unsigned)h1 << 16) | h0;
      a2h[mt][ks2][sub+1] = ((unsigned)h3 << 16) | h2;
      a2l[mt][ks2][sub]   = ((unsigned)l1 << 16) | l0;
      a2l[mt][ks2][sub+1] = ((unsigned)l3 << 16) | l2;
    }
  }

  // L3 mma: D2[128x32] = A2[128x64] * W3[64x32]
  float d2[2][4][4];
  #pragma unroll
  for (int mt = 0; mt < 2; mt++)
    #pragma unroll
    for (int nt = 0; nt < 4; nt++)
      #pragma unroll
      for (int q = 0; q < 4; q++) d2[mt][nt][q] = 0.0f;
  #pragma unroll
  for (int term = 0; term < 3; term++) {
    const unsigned* B = (term == 1) ? sW3l : sW3h;
    bool useAl = (term == 2);
    #pragma unroll
    for (int ks = 0; ks < 4; ks++) {
      #pragma unroll
      for (int nt = 0; nt < 4; nt++) {
        int n = nt*8 + g;
        unsigned b0 = B[n*36 + ks*8 + tig];
        unsigned b1 = B[n*36 + ks*8 + 4 + tig];
        mma16816(d2[0][nt], useAl ? a2l[0][ks] : a2h[0][ks], b0, b1);
        mma16816(d2[1][nt], useAl ? a2l[1][ks] : a2h[1][ks], b0, b1);
      }
    }
  }

  // stage D2 [row][32] stride 34 (EVEN: float2 reads 8B-aligned; 128*34 = 4352)
  float* sD = reinterpret_cast<float*>(pool);
  #pragma unroll
  for (int mt = 0; mt < 2; mt++) {
    int r0 = wid*32 + mt*16 + g;
    #pragma unroll
    for (int nt = 0; nt < 4; nt++) {
      int c = nt*8 + tig*2;
      sD[r0*34 + c]       = d2[mt][nt][0];
      sD[r0*34 + c + 1]   = d2[mt][nt][1];
      sD[(r0+8)*34 + c]   = d2[mt][nt][2];
      sD[(r0+8)*34 + c+1] = d2[mt][nt][3];
    }
  }
  __syncthreads();

  if (!act) return;
  unsigned* vrow = g_vmax + (size_t)pv * 32;
  #pragma unroll
  for (int k2 = 0; k2 < 16; k2++) {
    u64 v = relu2(add2(lds2(sD + tid*34 + 2*k2), lds2(sb3 + 2*k2)));
    float lo, hi; unpack2(v, lo, hi);
    g_pf2[(size_t)k2*N + i] = make_float2(lo, hi);
    atomicMax(vrow + 2*k2,     __float_as_uint(lo));
    atomicMax(vrow + 2*k2 + 1, __float_as_uint(hi));
  }
}

// ---- per-voxel MLP + aux head, 2 voxels/thread (R8) ----
__global__ void __launch_bounds__(128, 3) k_vox(float* __restrict__ aux_out,
                                                const float* __restrict__ ax_w2, int V) {
  __shared__ __align__(16) float s1[32*32], s2[32*32], sa[32*32], sa2[32*20];
  __shared__ __align__(16) float sb1v[32], sb2v[32], sba[32];
  __shared__ float so[256*21];
  int t = blockIdx.x * 128 + threadIdx.x;
  int j0 = 2*t, j1 = j0 + 1;
  bool act0 = j0 < V, act1 = j1 < V;
  for (int q = threadIdx.x; q < 32*32; q += 128) { s1[q] = g_w_ve1[q]; s2[q] = g_w_ve2[q]; sa[q] = g_w_ax1[q]; }
  for (int q = threadIdx.x; q < 32*20; q += 128) sa2[q] = ax_w2[q];
  if (threadIdx.x < 32) { sb1v[threadIdx.x] = g_b_ve1[threadIdx.x]; sb2v[threadIdx.x] = g_b_ve2[threadIdx.x]; sba[threadIdx.x] = g_b_ax1[threadIdx.x]; }
  __syncthreads();
  if (act0) {
    int jj1 = act1 ? j1 : j0;
    u64 v10[16], v11[16];
    #pragma unroll
    for (int o2 = 0; o2 < 16; o2++) { u64 b = lds2(sb1v + 2*o2); v10[o2] = b; v11[o2] = b; }
    const uint4* vr0 = reinterpret_cast<const uint4*>(g_vmax + (size_t)j0 * 32);
    const uint4* vr1 = reinterpret_cast<const uint4*>(g_vmax + (size_t)jj1 * 32);
    #pragma unroll
    for (int q = 0; q < 8; q++) {
      uint4 A = vr0[q], B = vr1[q];
      float a4[4] = { __uint_as_float(A.x), __uint_as_float(A.y), __uint_as_float(A.z), __uint_as_float(A.w) };
      float b4[4] = { __uint_as_float(B.x), __uint_as_float(B.y), __uint_as_float(B.z), __uint_as_float(B.w) };
      #pragma unroll
      for (int jj = 0; jj < 4; jj++) {
        u64 ea = bcast2(a4[jj]), fb = bcast2(b4[jj]);
        const float* row = s1 + (q*4 + jj)*32;
        #pragma unroll
        for (int o4 = 0; o4 < 32; o4 += 4) {
          u64 w0, w1; ld2q(row + o4, w0, w1);
          v10[o4/2] = fma2(ea, w0, v10[o4/2]); v10[o4/2+1] = fma2(ea, w1, v10[o4/2+1]);
          v11[o4/2] = fma2(fb, w0, v11[o4/2]); v11[o4/2+1] = fma2(fb, w1, v11[o4/2+1]);
        }
      }
    }
    #pragma unroll
    for (int o2 = 0; o2 < 16; o2++) { v10[o2] = relu2(v10[o2]); v11[o2] = relu2(v11[o2]); }
    {
      u64 vf0[16], vf1[16];
      #pragma unroll
      for (int o2 = 0; o2 < 16; o2++) { u64 b = lds2(sb2v + 2*o2); vf0[o2] = b; vf1[o2] = b; }
      #pragma unroll
      for (int k2 = 0; k2 < 16; k2++) {
        float e0, e1; unpack2(v10[k2], e0, e1);
        float f0, f1; unpack2(v11[k2], f0, f1);
        {
          const float* row = s2 + (2*k2)*32;
          u64 ea = bcast2(e0), fa = bcast2(f0);
          #pragma unroll
          for (int o4 = 0; o4 < 32; o4 += 4) {
            u64 w0, w1; ld2q(row + o4, w0, w1);
            vf0[o4/2] = fma2(ea, w0, vf0[o4/2]); vf0[o4/2+1] = fma2(ea, w1, vf0[o4/2+1]);
            vf1[o4/2] = fma2(fa, w0, vf1[o4/2]); vf1[o4/2+1] = fma2(fa, w1, vf1[o4/2+1]);
          }
        }
        {
          const float* row = s2 + (2*k2+1)*32;
          u64 eb = bcast2(e1), fb = bcast2(f1);
          #pragma unroll
          for (int o4 = 0; o4 < 32; o4 += 4) {
            u64 w0, w1; ld2q(row + o4, w0, w1);
            vf0[o4/2] = fma2(eb, w0, vf0[o4/2]); vf0[o4/2+1] = fma2(eb, w1, vf0[o4/2+1]);
            vf1[o4/2] = fma2(fb, w0, vf1[o4/2]); vf1[o4/2+1] = fma2(fb, w1, vf1[o4/2+1]);
          }
        }
      }
      float* vfr0 = g_vf + (size_t)j0 * 32;
      float* vfr1 = g_vf + (size_t)jj1 * 32;
      #pragma unroll
      for (int o2 = 0; o2 < 16; o2++) {
        u64 v = relu2(vf0[o2]);
        float lo, hi; unpack2(v, lo, hi);
        *reinterpret_cast<float2*>(vfr0 + 2*o2) = make_float2(lo, hi);
        if (act1) {
          v = relu2(vf1[o2]);
          unpack2(v, lo, hi);
          *reinterpret_cast<float2*>(vfr1 + 2*o2) = make_float2(lo, hi);
        }
      }
    }
    {
      u64 ah0[16], ah1[16];
      #pragma unroll
      for (int o2 = 0; o2 < 16; o2++) { u64 b = lds2(sba + 2*o2); ah0[o2] = b; ah1[o2] = b; }
      #pragma unroll
      for (int k2 = 0; k2 < 16; k2++) {
        float e0, e1; unpack2(v10[k2], e0, e1);
        float f0, f1; unpack2(v11[k2], f0, f1);
        {
          const float* row = sa + (2*k2)*32;
          u64 ea = bcast2(e0), fa = bcast2(f0);
          #pragma unroll
          for (int o4 = 0; o4 < 32; o4 += 4) {
            u64 w0, w1; ld2q(row + o4, w0, w1);
            ah0[o4/2] = fma2(ea, w0, ah0[o4/2]); ah0[o4/2+1] = fma2(ea, w1, ah0[o4/2+1]);
            ah1[o4/2] = fma2(fa, w0, ah1[o4/2]); ah1[o4/2+1] = fma2(fa, w1, ah1[o4/2+1]);
          }
        }
        {
          const float* row = sa + (2*k2+1)*32;
          u64 eb = bcast2(e1), fb = bcast2(f1);
          #pragma unroll
          for (int o4 = 0; o4 < 32; o4 += 4) {
            u64 w0, w1; ld2q(row + o4, w0, w1);
            ah0[o4/2] = fma2(eb, w0, ah0[o4/2]); ah0[o4/2+1] = fma2(eb, w1, ah0[o4/2+1]);
            ah1[o4/2] = fma2(fb, w0, ah1[o4/2]); ah1[o4/2+1] = fma2(fb, w1, ah1[o4/2+1]);
          }
        }
      }
      u64 ac0[10], ac1[10];
      #pragma unroll
      for (int o2 = 0; o2 < 10; o2++) { ac0[o2] = 0; ac1[o2] = 0; }
      #pragma unroll
      for (int k2 = 0; k2 < 16; k2++) {
        u64 hv0 = relu2(ah0[k2]), hv1 = relu2(ah1[k2]);
        float e0, e1; unpack2(hv0, e0, e1);
        float f0, f1; unpack2(hv1, f0, f1);
        {
          const float* row = sa2 + (2*k2)*20;
          u64 ea = bcast2(e0), fa = bcast2(f0);
          #pragma unroll
          for (int o2 = 0; o2 < 10; o2++) {
            u64 w = lds2(row + 2*o2);
            ac0[o2] = fma2(ea, w, ac0[o2]); ac1[o2] = fma2(fa, w, ac1[o2]);
          }
        }
        {
          const float* row = sa2 + (2*k2+1)*20;
          u64 eb = bcast2(e1), fb = bcast2(f1);
          #pragma unroll
          for (int o2 = 0; o2 < 10; o2++) {
            u64 w = lds2(row + 2*o2);
            ac0[o2] = fma2(eb, w, ac0[o2]); ac1[o2] = fma2(fb, w, ac1[o2]);
          }
        }
      }
      int r0 = 2*threadIdx.x, r1 = r0 + 1;
      #pragma unroll
      for (int o2 = 0; o2 < 10; o2++) {
        float lo, hi; unpack2(ac0[o2], lo, hi);
        so[r0*21 + 2*o2] = lo; so[r0*21 + 2*o2 + 1] = hi;
        unpack2(ac1[o2], lo, hi);
        so[r1*21 + 2*o2] = lo; so[r1*21 + 2*o2 + 1] = hi;
      }
    }
  }
  __syncthreads();
  int base = blockIdx.x * 256;
  int rows = V - base; if (rows > 256) rows = 256;
  if (rows > 0)
    for (int q = threadIdx.x; q < rows*20; q += 128)
      aux_out[(size_t)base*20 + q] = so[(q/20)*21 + (q%20)];
}

// ---- fuse 64->64 via mma.sync bf16 hi/lo; 128 points/CTA (R14 winner) ----
__global__ void __launch_bounds__(128) k_fuse(const float* __restrict__ points, int N) {
  extern __shared__ unsigned pool[];
  unsigned* sAh = pool;
  unsigned* sAl = pool + 4352;
  unsigned* sBh = pool + 8704;
  unsigned* sBl = pool + 11008;
  __shared__ float sbias[64];
  __shared__ float swsum[4][64];
  __shared__ int   swb[4];

  int tid = threadIdx.x;
  int lane = tid & 31, wid = tid >> 5;
  int i = blockIdx.x * 128 + tid;
  bool act = i < N;
  int b = -1, pv = 0;
  if (act) { pv = g_pv[i]; b = (int)points[(size_t)i*5]; }

  float in[64];
  if (act) {
    const float4* vr = reinterpret_cast<const float4*>(g_vf + (size_t)pv * 32);
    #pragma unroll
    for (int q = 0; q < 8; q++) {
      float4 A = vr[q];
      in[4*q]=A.x; in[4*q+1]=A.y; in[4*q+2]=A.z; in[4*q+3]=A.w;
    }
    #pragma unroll
    for (int c2 = 0; c2 < 16; c2++) {
      float2 v = g_pf2[(size_t)c2*N + i];
      in[32+2*c2] = v.x; in[32+2*c2+1] = v.y;
    }
  } else {
    #pragma unroll
    for (int c = 0; c < 64; c++) in[c] = 0.0f;
  }

  for (int q = tid; q < 64*32; q += 128) {
    int n = q >> 5, kp = q & 31;
    sBh[n*36 + kp] = g_fu_bh2[q];
    sBl[n*36 + kp] = g_fu_bl2[q];
  }
  if (tid < 64) sbias[tid] = g_b_fu[tid];

  #pragma unroll
  for (int kp = 0; kp < 32; kp++) {
    float x0 = in[2*kp], x1 = in[2*kp+1];
    unsigned short h0, l0, h1, l1;
    bfsplit(x0, h0, l0); bfsplit(x1, h1, l1);
    sAh[kp*136 + tid] = ((unsigned)h1 << 16) | h0;
    sAl[kp*136 + tid] = ((unsigned)l1 << 16) | l0;
  }
  __syncthreads();

  int g = lane >> 2, tig = lane & 3;
  float d[2][8][4];
  #pragma unroll
  for (int mt = 0; mt < 2; mt++)
    #pragma unroll
    for (int nt = 0; nt < 8; nt++)
      #pragma unroll
      for (int q = 0; q < 4; q++) d[mt][nt][q] = 0.0f;

  #pragma unroll
  for (int term = 0; term < 3; term++) {
    const unsigned* A = (term == 2) ? sAl : sAh;
    const unsigned* B = (term == 1) ? sBl : sBh;
    #pragma unroll
    for (int ks = 0; ks < 4; ks++) {
      unsigned a[2][4];
      #pragma unroll
      for (int mt = 0; mt < 2; mt++) {
        int r0 = wid*32 + mt*16 + g;
        a[mt][0] = A[(ks*8 + tig)*136 + r0];
        a[mt][1] = A[(ks*8 + tig)*136 + r0 + 8];
        a[mt][2] = A[(ks*8 + 4 + tig)*136 + r0];
        a[mt][3] = A[(ks*8 + 4 + tig)*136 + r0 + 8];
      }
      #pragma unroll
      for (int nt = 0; nt < 8; nt++) {
        int n = nt*8 + g;
        unsigned b0 = B[n*36 + ks*8 + tig];
        unsigned b1 = B[n*36 + ks*8 + 4 + tig];
        mma16816(d[0][nt], a[0], b0, b1);
        mma16816(d[1][nt], a[1], b0, b1);
      }
    }
  }
  __syncthreads();

  float* sD = reinterpret_cast<float*>(pool);
  #pragma unroll
  for (int mt = 0; mt < 2; mt++) {
    int r0 = wid*32 + mt*16 + g;
    #pragma unroll
    for (int nt = 0; nt < 8; nt++) {
      int c = nt*8 + tig*2;
      sD[r0*65 + c]       = d[mt][nt][0];
      sD[r0*65 + c + 1]   = d[mt][nt][1];
      sD[(r0+8)*65 + c]   = d[mt][nt][2];
      sD[(r0+8)*65 + c+1] = d[mt][nt][3];
    }
  }
  __syncthreads();

  float dv[64];
  #pragma unroll
  for (int c = 0; c < 64; c++)
    dv[c] = act ? fmaxf(sD[tid*65 + c] + sbias[c], 0.0f) : 0.0f;
  if (act) {
    #pragma unroll
    for (int c2 = 0; c2 < 32; c2++)
      g_fused2[(size_t)c2*N + i] = make_float2(dv[2*c2], dv[2*c2+1]);
  }
  bool fast = (__match_any_sync(FULLM, b) == FULLM) && __all_sync(FULLM, b >= 0);
  if (lane == 0) swb[wid] = fast ? b : -1;
  if (fast) {
    #pragma unroll
    for (int c2 = 0; c2 < 32; c2++) {
      u64 v = pack2(dv[2*c2], dv[2*c2+1]);
      v = add2(v, __shfl_xor_sync(FULLM, v, 16));
      v = add2(v, __shfl_xor_sync(FULLM, v, 8));
      v = add2(v, __shfl_xor_sync(FULLM, v, 4));
      v = add2(v, __shfl_xor_sync(FULLM, v, 2));
      v = add2(v, __shfl_xor_sync(FULLM, v, 1));
      if (lane == 0) {
        float sl, sh; unpack2(v, sl, sh);
        swsum[wid][2*c2] = sl; swsum[wid][2*c2+1] = sh;
      }
    }
  } else if (act) {
    for (int c = 0; c < 64; c++) atomicAdd(&g_bsum[b*64 + c], dv[c]);
    atomicAdd(&g_bcnt[b], 1u);
  }
  __syncthreads();
  if (tid < 64) {
    int c = tid;
    int curb = -1; float cv = 0.0f;
    for (int w = 0; w < 4; w++) {
      int wb = swb[w];
      if (wb < 0) continue;
      if (wb != curb) { if (curb >= 0) atomicAdd(&g_bsum[curb*64 + c], cv); curb = wb; cv = 0.0f; }
      cv += swsum[w][c];
    }
    if (curb >= 0) atomicAdd(&g_bsum[curb*64 + c], cv);
  }
  if (tid == 0) {
    int curb = -1; unsigned cc = 0;
    for (int w = 0; w < 4; w++) {
      int wb = swb[w];
      if (wb < 0) continue;
      if (wb != curb) { if (curb >= 0) atomicAdd(&g_bcnt[curb], cc); curb = wb; cc = 0; }
      cc += 32;
    }
    if (curb >= 0) atomicAdd(&g_bcnt[curb], cc);
  }
}

// ---- SE gate ----
__global__ void k_se(const float* __restrict__ se_w1, const float* __restrict__ se_b1,
                     const float* __restrict__ se_w2, const float* __restrict__ se_b2) {
  __shared__ float mean[4*64], t1[16];
  int tid = threadIdx.x;
  int b = tid >> 6, c = tid & 63;
  mean[tid] = g_bsum[tid] / fmaxf((float)g_bcnt[b], 1.0f);
  __syncthreads();
  if (tid < 16) {
    int bb = tid >> 2, jj = tid & 3;
    float a = se_b1[jj];
    for (int k = 0; k < 64; k++) a += mean[bb*64 + k] * se_w1[k*4 + jj];
    t1[tid] = fmaxf(a, 0.0f);
  }
  __syncthreads();
  {
    float a = se_b2[c];
    #pragma unroll
    for (int jj = 0; jj < 4; jj++) a += t1[b*4 + jj] * se_w2[jj*64 + c];
    g_gp1[tid] = 1.0f + 1.0f / (1.0f + expf(-a));
  }
}

// ---- classifier head: gate-scale, 64->32->20, 2 points/thread (R14 scalar) ----
__global__ void __launch_bounds__(128, 4) k_out(const float* __restrict__ points,
                                                const float* __restrict__ cl_w2,
                                                float* __restrict__ out, int N) {
  __shared__ __align__(16) float sw1[64*32], sw2[32*20], sb1c[32];
  __shared__ __align__(8) float sg[256];
  __shared__ float so[256*21];
  int t = blockIdx.x * 128 + threadIdx.x;
  int i0 = 2*t, i1 = i0 + 1;
  bool act0 = i0 < N, act1 = i1 < N;
  int b0 = 0, b1 = 0;
  if (act0) b0 = (int)points[(size_t)i0*5];
  if (act1) b1 = (int)points[(size_t)i1*5]; else b1 = b0;
  for (int q = threadIdx.x; q < 64*32; q += 128) sw1[q] = g_w_cl1[q];
  for (int q = threadIdx.x; q < 32*20; q += 128) sw2[q] = cl_w2[q];
  if (threadIdx.x < 32) sb1c[threadIdx.x] = g_b_cl1[threadIdx.x];
  for (int q = threadIdx.x; q < 256; q += 128) sg[q] = g_gp1[q];
  __syncthreads();
  if (act0) {
    const float* ga = sg + b0*64;
    const float* gb = sg + b1*64;
    u64 h0[16], h1[16];
    #pragma unroll
    for (int o2 = 0; o2 < 16; o2++) { u64 b = lds2(sb1c + 2*o2); h0[o2] = b; h1[o2] = b; }
    #pragma unroll
    for (int k2 = 0; k2 < 32; k2++) {
      float2 fv0 = g_fused2[(size_t)k2*N + i0];
      float2 fv1 = act1 ? g_fused2[(size_t)k2*N + i1] : make_float2(0.f, 0.f);
      float2 gva = *reinterpret_cast<const float2*>(ga + 2*k2);
      float2 gvb = *reinterpret_cast<const float2*>(gb + 2*k2);
      float e0 = fv0.x * gva.x, e1 = fv0.y * gva.y;
      float f0 = fv1.x * gvb.x, f1 = fv1.y * gvb.y;
      {
        const float* row = sw1 + (2*k2)*32;
        u64 ea = bcast2(e0), fa = bcast2(f0);
        #pragma unroll
        for (int o4 = 0; o4 < 32; o4 += 4) {
          u64 w0, w1; ld2q(row + o4, w0, w1);
          h0[o4/2]   = fma2(ea, w0, h0[o4/2]);   h0[o4/2+1] = fma2(ea, w1, h0[o4/2+1]);
          h1[o4/2]   = fma2(fa, w0, h1[o4/2]);   h1[o4/2+1] = fma2(fa, w1, h1[o4/2+1]);
        }
      }
      {
        const float* row = sw1 + (2*k2+1)*32;
        u64 eb = bcast2(e1), fb = bcast2(f1);
        #pragma unroll
        for (int o4 = 0; o4 < 32; o4 += 4) {
          u64 w0, w1; ld2q(row + o4, w0, w1);
          h0[o4/2]   = fma2(eb, w0, h0[o4/2]);   h0[o4/2+1] = fma2(eb, w1, h0[o4/2+1]);
          h1[o4/2]   = fma2(fb, w0, h1[o4/2]);   h1[o4/2+1] = fma2(fb, w1, h1[o4/2+1]);
        }
      }
    }
    #pragma unroll
    for (int o2 = 0; o2 < 16; o2++) { h0[o2] = relu2(h0[o2]); h1[o2] = relu2(h1[o2]); }
    int r0 = 2*threadIdx.x, r1 = r0 + 1;
    #pragma unroll
    for (int half = 0; half < 2; half++) {
      u64 a0[5], a1[5];
      #pragma unroll
      for (int q = 0; q < 5; q++) { a0[q] = 0; a1[q] = 0; }
      #pragma unroll
      for (int k2 = 0; k2 < 16; k2++) {
        float e0, e1; unpack2(h0[k2], e0, e1);
        float f0, f1; unpack2(h1[k2], f0, f1);
        {
          const float* row = sw2 + (2*k2)*20 + half*10;
          u64 ea = bcast2(e0), fa = bcast2(f0);
          #pragma unroll
          for (int q = 0; q < 5; q++) {
            u64 w = lds2(row + 2*q);
            a0[q] = fma2(ea, w, a0[q]); a1[q] = fma2(fa, w, a1[q]);
          }
        }
        {
          const float* row = sw2 + (2*k2+1)*20 + half*10;
          u64 eb = bcast2(e1), fb = bcast2(f1);
          #pragma unroll
          for (int q = 0; q < 5; q++) {
            u64 w = lds2(row + 2*q);
            a0[q] = fma2(eb, w, a0[q]); a1[q] = fma2(fb, w, a1[q]);
          }
        }
      }
      #pragma unroll
      for (int q = 0; q < 5; q++) {
        float lo, hi; unpack2(a0[q], lo, hi);
        so[r0*21 + half*10 + 2*q] = lo; so[r0*21 + half*10 + 2*q + 1] = hi;
        unpack2(a1[q], lo, hi);
        so[r1*21 + half*10 + 2*q] = lo; so[r1*21 + half*10 + 2*q + 1] = hi;
      }
    }
  }
  __syncthreads();
  int base = blockIdx.x * 256;
  int rows = N - base; if (rows > 256) rows = 256;
  if (rows > 0)
    for (int q = threadIdx.x; q < rows*20; q += 128)
      out[(size_t)base*20 + q] = so[(q/20)*21 + (q%20)];
}

extern "C" void kernel_launch(void* const* d_in, const int* in_sizes, int n_in,
                              void* d_out, int out_size) {
  const float* points = (const float*)d_in[0];
  int N = in_sizes[0] / 5;
  int V = (out_size - N * 20) / 20;
  float* out = (float*)d_out;
  float* aux_out = out + (size_t)N * 20;

  WP wp;
  wp.pe_w1 = (const float*)d_in[2];  wp.pe_g1 = (const float*)d_in[3];  wp.pe_b1 = (const float*)d_in[4];
  wp.pe_w2 = (const float*)d_in[5];  wp.pe_g2 = (const float*)d_in[6];  wp.pe_b2 = (const float*)d_in[7];
  wp.pe_w3 = (const float*)d_in[8];  wp.pe_g3 = (const float*)d_in[9];  wp.pe_b3 = (const float*)d_in[10];
  wp.ve_w1 = (const float*)d_in[11]; wp.ve_g1 = (const float*)d_in[12]; wp.ve_b1 = (const float*)d_in[13];
  wp.ve_w2 = (const float*)d_in[14]; wp.ve_g2 = (const float*)d_in[15]; wp.ve_b2 = (const float*)d_in[16];
  wp.fu_w  = (const float*)d_in[17]; wp.fu_g  = (const float*)d_in[18]; wp.fu_b  = (const float*)d_in[19];
  wp.cl_w1 = (const float*)d_in[24]; wp.cl_g1 = (const float*)d_in[25]; wp.cl_b1 = (const float*)d_in[26];
  wp.ax_w1 = (const float*)d_in[28]; wp.ax_g1 = (const float*)d_in[29]; wp.ax_b1 = (const float*)d_in[30];
  wp.pv_raw = (const int*)d_in[1];

  static int smem_set = 0;
  if (!smem_set) {
    cudaFuncSetAttribute(k_fuse, cudaFuncAttributeMaxDynamicSharedMemorySize, 13312*4);
    smem_set = 1;
  }

  k_prep<<<1, 256>>>(wp);

  int tot = 32 * V; if (N > tot) tot = N;
  k_init<<<(tot + 255) / 256, 256>>>(d_in[1], N, V);

  k_points<<<(N + 127) / 128, 128, 9216*4>>>(points, N);
  k_vox<<<(V + 255) / 256, 128>>>(aux_out, (const float*)d_in[31], V);
  k_fuse<<<(N + 127) / 128, 128, 13312*4>>>(points, N);
  k_se<<<1, 256>>>((const float*)d_in[20], (const float*)d_in[21],
                   (const float*)d_in[22], (const float*)d_in[23]);
  k_out<<<(N + 255) / 256, 128>>>(points, (const float*)d_in[27], out, N);
}